// round 1
// baseline (speedup 1.0000x reference)
#include <cuda_runtime.h>

#define NB 4
#define NN 10000
#define NE 170000
#define FIN 256
#define FOUT 128
#define NH 4
#define MTOT (NB*NN)          /* 40000 */
#define CPN (NB*NH*FOUT)      /* 2048 floats per node row */
#define LEAKY 0.2f

// ---------------- scratch (static device memory; no allocs allowed) --------
__device__ float4 d_h[(size_t)NN * (CPN/4)];   // h, node-major: [n][b][head][f]  (82 MB)
__device__ float4 d_ev[NE];                    // exp(att) per edge, 4 heads packed
__device__ float4 d_ps[NN];                    // p_src per node, 4 heads
__device__ float4 d_pd[NN];                    // p_dst per node, 4 heads
__device__ int    d_rowptr[NN + 1];
__device__ float  d_vsrc[NH * FIN];
__device__ float  d_vdst[NH * FIN];
__device__ float  d_csrc[NH];
__device__ float  d_cdst[NH];

// ---------------- K0: fold attention vectors through the MLP weights ------
// v_src[h] = W_mlp[h] @ a_src[h]  (256-vector), c_src[h] = b_mlp[h]·a_src[h]
__global__ void prep_vecs(const float* __restrict__ Wm, const float* __restrict__ bm,
                          const float* __restrict__ Wa) {
    int h = blockIdx.x;
    int t = threadIdx.x;   // 256 threads, t = k index in [0,FIN)
    __shared__ float asrc[FOUT], adst[FOUT];
    if (t < FOUT) {
        asrc[t] = Wa[h * 2 * FOUT + t];
        adst[t] = Wa[h * 2 * FOUT + FOUT + t];
    }
    __syncthreads();
    const float* w = Wm + (size_t)h * FIN * FOUT + (size_t)t * FOUT;
    float s1 = 0.f, s2 = 0.f;
#pragma unroll 8
    for (int f = 0; f < FOUT; f++) {
        float wv = w[f];
        s1 += wv * asrc[f];
        s2 += wv * adst[f];
    }
    d_vsrc[h * FIN + t] = s1;
    d_vdst[h * FIN + t] = s2;
    if (t == 0) {
        float c1 = 0.f, c2 = 0.f;
        for (int f = 0; f < FOUT; f++) {
            float bv = bm[h * FOUT + f];
            c1 += bv * asrc[f];
            c2 += bv * adst[f];
        }
        d_csrc[h] = c1;
        d_cdst[h] = c2;
    }
}

// ---------------- K1: per-node scores, warp per node -----------------------
__global__ void node_scores(const float* __restrict__ Xl) {
    int gw = (blockIdx.x * blockDim.x + threadIdx.x) >> 5;
    int lane = threadIdx.x & 31;
    if (gw >= NN) return;
    const float* xr = Xl + (size_t)gw * FIN;
    float xv[8];
#pragma unroll
    for (int i = 0; i < 8; i++) xv[i] = xr[lane + 32 * i];
    float ps[NH], pd[NH];
#pragma unroll
    for (int h = 0; h < NH; h++) {
        float s1 = 0.f, s2 = 0.f;
#pragma unroll
        for (int i = 0; i < 8; i++) {
            int k = lane + 32 * i;
            s1 += xv[i] * d_vsrc[h * FIN + k];
            s2 += xv[i] * d_vdst[h * FIN + k];
        }
#pragma unroll
        for (int o = 16; o > 0; o >>= 1) {
            s1 += __shfl_down_sync(0xffffffffu, s1, o);
            s2 += __shfl_down_sync(0xffffffffu, s2, o);
        }
        ps[h] = s1;
        pd[h] = s2;
    }
    if (lane == 0) {
        d_ps[gw] = make_float4(ps[0] + d_csrc[0], ps[1] + d_csrc[1],
                               ps[2] + d_csrc[2], ps[3] + d_csrc[3]);
        d_pd[gw] = make_float4(pd[0] + d_cdst[0], pd[1] + d_cdst[1],
                               pd[2] + d_cdst[2], pd[3] + d_cdst[3]);
    }
}

// ---------------- K2: per-edge exp(clip(leaky_relu(s))) --------------------
__device__ __forceinline__ float att_act(float s) {
    float lr = s > 0.f ? s : LEAKY * s;
    lr = fminf(fmaxf(lr, -2.f), 2.f);
    return expf(lr);
}

__global__ void edge_exp(const int* __restrict__ src, const int* __restrict__ dst) {
    int e = blockIdx.x * blockDim.x + threadIdx.x;
    if (e >= NE) return;
    float4 a = d_ps[src[e]];
    float4 b = d_pd[dst[e]];
    d_ev[e] = make_float4(att_act(a.x + b.x), att_act(a.y + b.y),
                          att_act(a.z + b.z), att_act(a.w + b.w));
}

// ---------------- K2b: CSR row_ptr from sorted src -------------------------
__global__ void build_rowptr(const int* __restrict__ src) {
    int e = blockIdx.x * blockDim.x + threadIdx.x;
    if (e >= NE) return;
    int cur = src[e];
    int prev = (e == 0) ? -1 : src[e - 1];
    for (int n = prev + 1; n <= cur; n++) d_rowptr[n] = e;
    if (e == NE - 1)
        for (int n = cur + 1; n <= NN; n++) d_rowptr[n] = NE;
}

// ---------------- K3: the MLP GEMM  h = x @ W + b  (fp32, 128x128x16) ------
#define BM 128
#define BN 128
#define BK 16
__global__ __launch_bounds__(256, 2) void gemm_mlp(const float* __restrict__ X,
                                                   const float* __restrict__ Wm,
                                                   const float* __restrict__ bm) {
    __shared__ float As[BK][BM + 4];   // transposed A tile, pad for STS banks + 16B align
    __shared__ float Bs[BK][BN];
    const int hx = blockIdx.x;         // column tile == head (BN == FOUT)
    const int by = blockIdx.y;
    const int tid = threadIdx.x;
    const int tcol = tid & 15;
    const int trow = tid >> 4;
    const int row0 = by * BM;
    const float* Bp = Wm + (size_t)hx * FIN * FOUT;

    float acc[8][8];
#pragma unroll
    for (int i = 0; i < 8; i++)
#pragma unroll
        for (int j = 0; j < 8; j++) acc[i][j] = 0.f;

    for (int k0 = 0; k0 < FIN; k0 += BK) {
#pragma unroll
        for (int l = 0; l < 2; l++) {
            int id = tid + l * 256;
            int r = id >> 2;
            int c4 = (id & 3) * 4;
            int gr = row0 + r;
            float4 v = make_float4(0.f, 0.f, 0.f, 0.f);
            if (gr < MTOT) v = *(const float4*)(X + (size_t)gr * FIN + k0 + c4);
            As[c4 + 0][r] = v.x;
            As[c4 + 1][r] = v.y;
            As[c4 + 2][r] = v.z;
            As[c4 + 3][r] = v.w;
        }
#pragma unroll
        for (int l = 0; l < 2; l++) {
            int id = tid + l * 256;
            int r = id >> 5;
            int c = (id & 31) * 4;
            *(float4*)&Bs[r][c] = *(const float4*)(Bp + (size_t)(k0 + r) * FOUT + c);
        }
        __syncthreads();
#pragma unroll
        for (int k = 0; k < BK; k++) {
            float a[8], b[8];
            *(float4*)(a)     = *(const float4*)&As[k][trow * 8];
            *(float4*)(a + 4) = *(const float4*)&As[k][trow * 8 + 4];
            *(float4*)(b)     = *(const float4*)&Bs[k][tcol * 8];
            *(float4*)(b + 4) = *(const float4*)&Bs[k][tcol * 8 + 4];
#pragma unroll
            for (int i = 0; i < 8; i++)
#pragma unroll
                for (int j = 0; j < 8; j++) acc[i][j] = fmaf(a[i], b[j], acc[i][j]);
        }
        __syncthreads();
    }

    float bias[8];
#pragma unroll
    for (int j = 0; j < 8; j++) bias[j] = bm[hx * FOUT + tcol * 8 + j];
    float* Hs = (float*)d_h;
#pragma unroll
    for (int i = 0; i < 8; i++) {
        int gr = row0 + trow * 8 + i;
        if (gr >= MTOT) continue;
        int bb = gr / NN;
        int n = gr - bb * NN;
        // node-major layout: [n][b][head][f]  -> matches aggregation & output
        float* dp = Hs + (size_t)n * CPN + bb * (NH * FOUT) + hx * FOUT + tcol * 8;
        float4 v0 = make_float4(acc[i][0] + bias[0], acc[i][1] + bias[1],
                                acc[i][2] + bias[2], acc[i][3] + bias[3]);
        float4 v1 = make_float4(acc[i][4] + bias[4], acc[i][5] + bias[5],
                                acc[i][6] + bias[6], acc[i][7] + bias[7]);
        *(float4*)dp = v0;
        *(float4*)(dp + 4) = v1;
    }
}

// ---------------- K4: aggregation, block per node, no atomics --------------
#define CHK 128
__global__ __launch_bounds__(512) void aggregate(const int* __restrict__ dst,
                                                 float* __restrict__ out) {
    const int n = blockIdx.x;
    const int r0 = d_rowptr[n];
    const int r1 = d_rowptr[n + 1];
    const int t = threadIdx.x;
    const int hi = (t & 127) >> 5;       // head of this thread's float4
    __shared__ int sdst[CHK];
    __shared__ float4 sev[CHK];
    const float* evp = (const float*)sev;
    float4 acc = make_float4(0.f, 0.f, 0.f, 0.f);
    float dacc = 0.f;

    for (int base = r0; base < r1; base += CHK) {
        int cnt = min(CHK, r1 - base);
        __syncthreads();
        if (t < cnt) {
            sdst[t] = dst[base + t];
            sev[t] = d_ev[base + t];
        }
        __syncthreads();
#pragma unroll 4
        for (int i = 0; i < cnt; i++) {
            float w = evp[i * 4 + hi];
            float4 hv = d_h[(size_t)sdst[i] * (CPN / 4) + t];
            acc.x = fmaf(w, hv.x, acc.x);
            acc.y = fmaf(w, hv.y, acc.y);
            acc.z = fmaf(w, hv.z, acc.z);
            acc.w = fmaf(w, hv.w, acc.w);
            dacc += w;                   // denominator for this head, for free
        }
    }
    float inv = (r1 > r0) ? (1.0f / dacc) : 0.f;
    int bb = t >> 7;
    int rest = (t & 127) << 2;
    float4 o = make_float4(acc.x * inv, acc.y * inv, acc.z * inv, acc.w * inv);
    *(float4*)(out + (size_t)bb * NN * (NH * FOUT) + (size_t)n * (NH * FOUT) + rest) = o;
}

// ---------------------------------------------------------------------------
extern "C" void kernel_launch(void* const* d_in, const int* in_sizes, int n_in,
                              void* d_out, int out_size) {
    const float* x   = (const float*)d_in[0];   // (B, N, 256)
    const float* Wm  = (const float*)d_in[1];   // (H, 256, 128)
    const float* bm  = (const float*)d_in[2];   // (H, 128)
    const float* Wa  = (const float*)d_in[3];   // (H, 256, 1)
    const int*   src = (const int*)d_in[4];     // (E,)  sorted
    const int*   dst = (const int*)d_in[5];     // (E,)
    float* out = (float*)d_out;                 // (B, N, 512)

    prep_vecs<<<NH, 256>>>(Wm, bm, Wa);
    node_scores<<<(NN * 32 + 255) / 256, 256>>>(x + (size_t)(NB - 1) * NN * FIN);
    edge_exp<<<(NE + 255) / 256, 256>>>(src, dst);
    build_rowptr<<<(NE + 255) / 256, 256>>>(src);
    dim3 gg(NH, (MTOT + BM - 1) / BM);
    gemm_mlp<<<gg, 256>>>(x, Wm, bm);
    aggregate<<<NN, 512>>>(dst, out);
}

// round 3
// speedup vs baseline: 1.4518x; 1.4518x over previous
#include <cuda_runtime.h>
#include <cuda_bf16.h>
#include <cstdint>

#define NB 4
#define NN 10000
#define NE 170000
#define FIN 256
#define FOUT 128
#define NH 4
#define MTOT (NB*NN)          /* 40000 */
#define CPN (NB*NH*FOUT)      /* 2048 floats per node row */
#define LEAKY 0.2f

// ---------------- scratch (static device memory; no allocs allowed) --------
__device__ float4 d_h[(size_t)NN * (CPN/4)];   // h, node-major: [n][b][head][f]  (82 MB)
__device__ float4 d_ev[NE];                    // exp(att) per edge, 4 heads packed
__device__ float4 d_ps[NN];
__device__ float4 d_pd[NN];
__device__ int    d_rowptr[NN + 1];
__device__ float  d_vsrc[NH * FIN];
__device__ float  d_vdst[NH * FIN];
__device__ float  d_csrc[NH];
__device__ float  d_cdst[NH];
// bf16 split operands for the tensor-core GEMM
__device__ __nv_bfloat16 d_Ahi[(size_t)MTOT * FIN];   // [row][k]
__device__ __nv_bfloat16 d_Alo[(size_t)MTOT * FIN];
__device__ __nv_bfloat16 d_Bhi[NH * FOUT * FIN];      // [h][n][k]  (col-major B for mma)
__device__ __nv_bfloat16 d_Blo[NH * FOUT * FIN];

// ---------------- K-1: bf16 hi/lo split of x and W -------------------------
__global__ void conv_x(const float* __restrict__ x) {
    int i = blockIdx.x * blockDim.x + threadIdx.x;
    if (i >= MTOT * FIN / 4) return;
    float4 v = ((const float4*)x)[i];
    __nv_bfloat16 h0 = __float2bfloat16(v.x), h1 = __float2bfloat16(v.y);
    __nv_bfloat16 h2 = __float2bfloat16(v.z), h3 = __float2bfloat16(v.w);
    __nv_bfloat162 hi01, hi23, lo01, lo23;
    hi01.x = h0; hi01.y = h1; hi23.x = h2; hi23.y = h3;
    lo01.x = __float2bfloat16(v.x - __bfloat162float(h0));
    lo01.y = __float2bfloat16(v.y - __bfloat162float(h1));
    lo23.x = __float2bfloat16(v.z - __bfloat162float(h2));
    lo23.y = __float2bfloat16(v.w - __bfloat162float(h3));
    ((__nv_bfloat162*)d_Ahi)[2 * i]     = hi01;
    ((__nv_bfloat162*)d_Ahi)[2 * i + 1] = hi23;
    ((__nv_bfloat162*)d_Alo)[2 * i]     = lo01;
    ((__nv_bfloat162*)d_Alo)[2 * i + 1] = lo23;
}

__global__ void conv_w(const float* __restrict__ Wm) {
    int i = blockIdx.x * blockDim.x + threadIdx.x;   // [h][k][f]
    if (i >= NH * FIN * FOUT) return;
    int h = i >> 15;
    int rem = i & 32767;
    int k = rem >> 7;
    int f = rem & 127;
    float w = Wm[i];
    __nv_bfloat16 hi = __float2bfloat16(w);
    float lo = w - __bfloat162float(hi);
    size_t o = ((size_t)h * FOUT + f) * FIN + k;     // [h][n][k]
    d_Bhi[o] = hi;
    d_Blo[o] = __float2bfloat16(lo);
}

// ---------------- K0: fold attention vectors through the MLP weights ------
__global__ void prep_vecs(const float* __restrict__ Wm, const float* __restrict__ bm,
                          const float* __restrict__ Wa) {
    int h = blockIdx.x;
    int t = threadIdx.x;
    __shared__ float asrc[FOUT], adst[FOUT];
    if (t < FOUT) {
        asrc[t] = Wa[h * 2 * FOUT + t];
        adst[t] = Wa[h * 2 * FOUT + FOUT + t];
    }
    __syncthreads();
    const float* w = Wm + (size_t)h * FIN * FOUT + (size_t)t * FOUT;
    float s1 = 0.f, s2 = 0.f;
#pragma unroll 8
    for (int f = 0; f < FOUT; f++) {
        float wv = w[f];
        s1 += wv * asrc[f];
        s2 += wv * adst[f];
    }
    d_vsrc[h * FIN + t] = s1;
    d_vdst[h * FIN + t] = s2;
    if (t == 0) {
        float c1 = 0.f, c2 = 0.f;
        for (int f = 0; f < FOUT; f++) {
            float bv = bm[h * FOUT + f];
            c1 += bv * asrc[f];
            c2 += bv * adst[f];
        }
        d_csrc[h] = c1;
        d_cdst[h] = c2;
    }
}

// ---------------- K1: per-node scores, warp per node -----------------------
__global__ void node_scores(const float* __restrict__ Xl) {
    int gw = (blockIdx.x * blockDim.x + threadIdx.x) >> 5;
    int lane = threadIdx.x & 31;
    if (gw >= NN) return;
    const float* xr = Xl + (size_t)gw * FIN;
    float xv[8];
#pragma unroll
    for (int i = 0; i < 8; i++) xv[i] = xr[lane + 32 * i];
    float ps[NH], pd[NH];
#pragma unroll
    for (int h = 0; h < NH; h++) {
        float s1 = 0.f, s2 = 0.f;
#pragma unroll
        for (int i = 0; i < 8; i++) {
            int k = lane + 32 * i;
            s1 += xv[i] * d_vsrc[h * FIN + k];
            s2 += xv[i] * d_vdst[h * FIN + k];
        }
#pragma unroll
        for (int o = 16; o > 0; o >>= 1) {
            s1 += __shfl_down_sync(0xffffffffu, s1, o);
            s2 += __shfl_down_sync(0xffffffffu, s2, o);
        }
        ps[h] = s1;
        pd[h] = s2;
    }
    if (lane == 0) {
        d_ps[gw] = make_float4(ps[0] + d_csrc[0], ps[1] + d_csrc[1],
                               ps[2] + d_csrc[2], ps[3] + d_csrc[3]);
        d_pd[gw] = make_float4(pd[0] + d_cdst[0], pd[1] + d_cdst[1],
                               pd[2] + d_cdst[2], pd[3] + d_cdst[3]);
    }
}

// ---------------- K2: per-edge exp(clip(leaky_relu(s))) --------------------
__device__ __forceinline__ float att_act(float s) {
    float lr = s > 0.f ? s : LEAKY * s;
    lr = fminf(fmaxf(lr, -2.f), 2.f);
    return expf(lr);
}

__global__ void edge_exp(const int* __restrict__ src, const int* __restrict__ dst) {
    int e = blockIdx.x * blockDim.x + threadIdx.x;
    if (e >= NE) return;
    float4 a = d_ps[src[e]];
    float4 b = d_pd[dst[e]];
    d_ev[e] = make_float4(att_act(a.x + b.x), att_act(a.y + b.y),
                          att_act(a.z + b.z), att_act(a.w + b.w));
}

// ---------------- K2b: CSR row_ptr from sorted src -------------------------
__global__ void build_rowptr(const int* __restrict__ src) {
    int e = blockIdx.x * blockDim.x + threadIdx.x;
    if (e >= NE) return;
    int cur = src[e];
    int prev = (e == 0) ? -1 : src[e - 1];
    for (int n = prev + 1; n <= cur; n++) d_rowptr[n] = e;
    if (e == NE - 1)
        for (int n = cur + 1; n <= NN; n++) d_rowptr[n] = NE;
}

// ---------------- K3: bf16-split GEMM via mma.sync (HMMA) ------------------
// CTA: 256 threads / 8 warps; tile M=128 x N=128 (one head); K chunk = 64.
// Warp tile 32x64 (2 Mtiles x 8 Ntiles of m16n8k16). 3 split passes.
#define GK 64
#define PADK 72                       /* padded k-stride (bf16) -> 144B rows  */
#define TILE_B (128 * PADK * 2)       /* 18432 bytes per smem tile */
#define OFF_AHI 0
#define OFF_ALO (TILE_B)
#define OFF_BHI (2 * TILE_B)
#define OFF_BLO (3 * TILE_B)
#define SM_TOTAL (4 * TILE_B)

#define MMA_BF16(d, a, b)                                                      \
    asm volatile("mma.sync.aligned.m16n8k16.row.col.f32.bf16.bf16.f32 "        \
                 "{%0,%1,%2,%3},{%4,%5,%6,%7},{%8,%9},{%0,%1,%2,%3};"          \
                 : "+f"((d)[0]), "+f"((d)[1]), "+f"((d)[2]), "+f"((d)[3])      \
                 : "r"((a)[0]), "r"((a)[1]), "r"((a)[2]), "r"((a)[3]),         \
                   "r"((b)[0]), "r"((b)[1]))

__global__ __launch_bounds__(256) void gemm_tc(const float* __restrict__ bm) {
    extern __shared__ char smem[];
    const int tid = threadIdx.x;
    const int hx = blockIdx.x;
    const int row0 = blockIdx.y * 128;
    const int wid = tid >> 5;
    const int lane = tid & 31;
    const int gid = lane >> 2;        // 0..7
    const int tig = lane & 3;         // 0..3
    const int warpM = wid & 3;        // 4 M subtiles of 32
    const int warpN = wid >> 2;       // 2 N subtiles of 64

    // gmem->smem mapping: row r (0..127), half = k offset 0/32
    const int r = tid >> 1;
    const int half = tid & 1;
    const bool inb = (row0 + r) < MTOT;
    const size_t aoff = (size_t)(row0 + r) * FIN + half * 32;
    const size_t boff = ((size_t)hx * FOUT + r) * FIN + half * 32;
    const uint32_t srow = (uint32_t)(r * (PADK * 2) + half * 64);
    const uint4 z4 = make_uint4(0u, 0u, 0u, 0u);

    float acc[2][8][4];
#pragma unroll
    for (int mt = 0; mt < 2; mt++)
#pragma unroll
        for (int nt = 0; nt < 8; nt++)
#pragma unroll
            for (int j = 0; j < 4; j++) acc[mt][nt][j] = 0.f;

    for (int kc = 0; kc < FIN / GK; kc++) {
        if (kc) __syncthreads();
        // ---- load the 4 tiles of this K chunk ----
#pragma unroll
        for (int j = 0; j < 4; j++) {
            size_t ge = (size_t)kc * GK + j * 8;
            uint32_t so = srow + j * 16;
            uint4 va = inb ? *(const uint4*)(d_Ahi + aoff + ge) : z4;
            uint4 vl = inb ? *(const uint4*)(d_Alo + aoff + ge) : z4;
            uint4 wh = *(const uint4*)(d_Bhi + boff + ge);
            uint4 wl = *(const uint4*)(d_Blo + boff + ge);
            *(uint4*)(smem + OFF_AHI + so) = va;
            *(uint4*)(smem + OFF_ALO + so) = vl;
            *(uint4*)(smem + OFF_BHI + so) = wh;
            *(uint4*)(smem + OFF_BLO + so) = wl;
        }
        __syncthreads();
        // ---- compute 4 k-steps of 16 ----
#pragma unroll
        for (int ks = 0; ks < 4; ks++) {
            const int k0 = ks * 16;
            const uint32_t kb = (uint32_t)((k0 + tig * 2) * 2);
            uint32_t bh[8][2], bl[8][2], af[2][4];
#pragma unroll
            for (int nt = 0; nt < 8; nt++) {
                uint32_t nb = (uint32_t)((warpN * 64 + nt * 8 + gid) * (PADK * 2)) + kb;
                bh[nt][0] = *(const uint32_t*)(smem + OFF_BHI + nb);
                bh[nt][1] = *(const uint32_t*)(smem + OFF_BHI + nb + 16);
                bl[nt][0] = *(const uint32_t*)(smem + OFF_BLO + nb);
                bl[nt][1] = *(const uint32_t*)(smem + OFF_BLO + nb + 16);
            }
            // pass 1+2: a_hi x (b_hi, b_lo)
#pragma unroll
            for (int mt = 0; mt < 2; mt++) {
                uint32_t mb = (uint32_t)((warpM * 32 + mt * 16 + gid) * (PADK * 2)) + kb;
                af[mt][0] = *(const uint32_t*)(smem + OFF_AHI + mb);
                af[mt][1] = *(const uint32_t*)(smem + OFF_AHI + mb + 8 * (PADK * 2));
                af[mt][2] = *(const uint32_t*)(smem + OFF_AHI + mb + 16);
                af[mt][3] = *(const uint32_t*)(smem + OFF_AHI + mb + 8 * (PADK * 2) + 16);
            }
#pragma unroll
            for (int mt = 0; mt < 2; mt++)
#pragma unroll
                for (int nt = 0; nt < 8; nt++) MMA_BF16(acc[mt][nt], af[mt], bh[nt]);
#pragma unroll
            for (int mt = 0; mt < 2; mt++)
#pragma unroll
                for (int nt = 0; nt < 8; nt++) MMA_BF16(acc[mt][nt], af[mt], bl[nt]);
            // pass 3: a_lo x b_hi
#pragma unroll
            for (int mt = 0; mt < 2; mt++) {
                uint32_t mb = (uint32_t)((warpM * 32 + mt * 16 + gid) * (PADK * 2)) + kb;
                af[mt][0] = *(const uint32_t*)(smem + OFF_ALO + mb);
                af[mt][1] = *(const uint32_t*)(smem + OFF_ALO + mb + 8 * (PADK * 2));
                af[mt][2] = *(const uint32_t*)(smem + OFF_ALO + mb + 16);
                af[mt][3] = *(const uint32_t*)(smem + OFF_ALO + mb + 8 * (PADK * 2) + 16);
            }
#pragma unroll
            for (int mt = 0; mt < 2; mt++)
#pragma unroll
                for (int nt = 0; nt < 8; nt++) MMA_BF16(acc[mt][nt], af[mt], bh[nt]);
        }
    }

    // ---- epilogue: bias add, store node-major into d_h ----
    float2 bias[8];
#pragma unroll
    for (int nt = 0; nt < 8; nt++)
        bias[nt] = *(const float2*)(bm + hx * FOUT + warpN * 64 + nt * 8 + tig * 2);

    float* Hs = (float*)d_h;
#pragma unroll
    for (int mt = 0; mt < 2; mt++) {
#pragma unroll
        for (int rh = 0; rh < 2; rh++) {              // row half: gid / gid+8
            int gr = row0 + warpM * 32 + mt * 16 + rh * 8 + gid;
            if (gr >= MTOT) continue;
            int bb = gr / NN;
            int n = gr - bb * NN;
            float* dp = Hs + (size_t)n * CPN + bb * (NH * FOUT) + hx * FOUT
                        + warpN * 64 + tig * 2;
#pragma unroll
            for (int nt = 0; nt < 8; nt++) {
                float2 v;
                v.x = acc[mt][nt][rh * 2 + 0] + bias[nt].x;
                v.y = acc[mt][nt][rh * 2 + 1] + bias[nt].y;
                *(float2*)(dp + nt * 8) = v;
            }
        }
    }
}

// ---------------- K4: aggregation, block per node, no atomics --------------
#define CHK 128
__global__ __launch_bounds__(512) void aggregate(const int* __restrict__ dst,
                                                 float* __restrict__ out) {
    const int n = blockIdx.x;
    const int r0 = d_rowptr[n];
    const int r1 = d_rowptr[n + 1];
    const int t = threadIdx.x;
    const int hi = (t & 127) >> 5;
    __shared__ int sdst[CHK];
    __shared__ float4 sev[CHK];
    const float* evp = (const float*)sev;
    float4 acc = make_float4(0.f, 0.f, 0.f, 0.f);
    float dacc = 0.f;

    for (int base = r0; base < r1; base += CHK) {
        int cnt = min(CHK, r1 - base);
        __syncthreads();
        if (t < cnt) {
            sdst[t] = dst[base + t];
            sev[t] = d_ev[base + t];
        }
        __syncthreads();
#pragma unroll 4
        for (int i = 0; i < cnt; i++) {
            float w = evp[i * 4 + hi];
            float4 hv = d_h[(size_t)sdst[i] * (CPN / 4) + t];
            acc.x = fmaf(w, hv.x, acc.x);
            acc.y = fmaf(w, hv.y, acc.y);
            acc.z = fmaf(w, hv.z, acc.z);
            acc.w = fmaf(w, hv.w, acc.w);
            dacc += w;
        }
    }
    float inv = (r1 > r0) ? (1.0f / dacc) : 0.f;
    int bb = t >> 7;
    int rest = (t & 127) << 2;
    float4 o = make_float4(acc.x * inv, acc.y * inv, acc.z * inv, acc.w * inv);
    *(float4*)(out + (size_t)bb * NN * (NH * FOUT) + (size_t)n * (NH * FOUT) + rest) = o;
}

// ---------------------------------------------------------------------------
extern "C" void kernel_launch(void* const* d_in, const int* in_sizes, int n_in,
                              void* d_out, int out_size) {
    const float* x   = (const float*)d_in[0];   // (B, N, 256)
    const float* Wm  = (const float*)d_in[1];   // (H, 256, 128)
    const float* bm  = (const float*)d_in[2];   // (H, 128)
    const float* Wa  = (const float*)d_in[3];   // (H, 256, 1)
    const int*   src = (const int*)d_in[4];     // (E,) sorted
    const int*   dst = (const int*)d_in[5];     // (E,)
    float* out = (float*)d_out;                 // (B, N, 512)

    cudaFuncSetAttribute(gemm_tc, cudaFuncAttributeMaxDynamicSharedMemorySize, SM_TOTAL);

    conv_x<<<(MTOT * FIN / 4 + 255) / 256, 256>>>(x);
    conv_w<<<(NH * FIN * FOUT + 255) / 256, 256>>>(Wm);
    prep_vecs<<<NH, 256>>>(Wm, bm, Wa);
    node_scores<<<(NN * 32 + 255) / 256, 256>>>(x + (size_t)(NB - 1) * NN * FIN);
    edge_exp<<<(NE + 255) / 256, 256>>>(src, dst);
    build_rowptr<<<(NE + 255) / 256, 256>>>(src);
    dim3 gg(NH, (MTOT + 127) / 128);
    gemm_tc<<<gg, 256, SM_TOTAL>>>(bm);
    aggregate<<<NN, 512>>>(dst, out);
}

// round 4
// speedup vs baseline: 1.6082x; 1.1077x over previous
#include <cuda_runtime.h>
#include <cuda_bf16.h>
#include <cuda_fp16.h>
#include <cstdint>

#define NB 4
#define NN 10000
#define NE 170000
#define FIN 256
#define FOUT 128
#define NH 4
#define MTOT (NB*NN)          /* 40000 */
#define CPN (NB*NH*FOUT)      /* 2048 values per node row */
#define LEAKY 0.2f

// ---------------- scratch (static device memory; no allocs allowed) --------
__device__ __half  d_h[(size_t)NN * CPN];      // h fp16, node-major [n][b][head][f] (41 MB)
__device__ float4  d_ev[NE];                   // exp(att) per edge, 4 heads packed
__device__ float4  d_ps[NN];
__device__ float4  d_pd[NN];
__device__ int     d_rowptr[NN + 1];
__device__ float   d_vsrc[NH * FIN];
__device__ float   d_vdst[NH * FIN];
__device__ float   d_csrc[NH];
__device__ float   d_cdst[NH];
// bf16 split W (transposed to [h][n][k]) for the tensor-core GEMM
__device__ __nv_bfloat16 d_Bhi[NH * FOUT * FIN];
__device__ __nv_bfloat16 d_Blo[NH * FOUT * FIN];

// ---------------- K-1: bf16 hi/lo split + transpose of W -------------------
__global__ void conv_w(const float* __restrict__ Wm) {
    int i = blockIdx.x * blockDim.x + threadIdx.x;   // [h][k][f]
    if (i >= NH * FIN * FOUT) return;
    int h = i >> 15;
    int rem = i & 32767;
    int k = rem >> 7;
    int f = rem & 127;
    float w = Wm[i];
    __nv_bfloat16 hi = __float2bfloat16(w);
    float lo = w - __bfloat162float(hi);
    size_t o = ((size_t)h * FOUT + f) * FIN + k;     // [h][n][k]
    d_Bhi[o] = hi;
    d_Blo[o] = __float2bfloat16(lo);
}

// ---------------- K0: fold attention vectors through the MLP weights ------
__global__ void prep_vecs(const float* __restrict__ Wm, const float* __restrict__ bm,
                          const float* __restrict__ Wa) {
    int h = blockIdx.x;
    int t = threadIdx.x;
    __shared__ float asrc[FOUT], adst[FOUT];
    if (t < FOUT) {
        asrc[t] = Wa[h * 2 * FOUT + t];
        adst[t] = Wa[h * 2 * FOUT + FOUT + t];
    }
    __syncthreads();
    const float* w = Wm + (size_t)h * FIN * FOUT + (size_t)t * FOUT;
    float s1 = 0.f, s2 = 0.f;
#pragma unroll 8
    for (int f = 0; f < FOUT; f++) {
        float wv = w[f];
        s1 += wv * asrc[f];
        s2 += wv * adst[f];
    }
    d_vsrc[h * FIN + t] = s1;
    d_vdst[h * FIN + t] = s2;
    if (t == 0) {
        float c1 = 0.f, c2 = 0.f;
        for (int f = 0; f < FOUT; f++) {
            float bv = bm[h * FOUT + f];
            c1 += bv * asrc[f];
            c2 += bv * adst[f];
        }
        d_csrc[h] = c1;
        d_cdst[h] = c2;
    }
}

// ---------------- K1: per-node scores, warp per node -----------------------
__global__ void node_scores(const float* __restrict__ Xl) {
    int gw = (blockIdx.x * blockDim.x + threadIdx.x) >> 5;
    int lane = threadIdx.x & 31;
    if (gw >= NN) return;
    const float* xr = Xl + (size_t)gw * FIN;
    float xv[8];
#pragma unroll
    for (int i = 0; i < 8; i++) xv[i] = xr[lane + 32 * i];
    float ps[NH], pd[NH];
#pragma unroll
    for (int h = 0; h < NH; h++) {
        float s1 = 0.f, s2 = 0.f;
#pragma unroll
        for (int i = 0; i < 8; i++) {
            int k = lane + 32 * i;
            s1 += xv[i] * d_vsrc[h * FIN + k];
            s2 += xv[i] * d_vdst[h * FIN + k];
        }
#pragma unroll
        for (int o = 16; o > 0; o >>= 1) {
            s1 += __shfl_down_sync(0xffffffffu, s1, o);
            s2 += __shfl_down_sync(0xffffffffu, s2, o);
        }
        ps[h] = s1;
        pd[h] = s2;
    }
    if (lane == 0) {
        d_ps[gw] = make_float4(ps[0] + d_csrc[0], ps[1] + d_csrc[1],
                               ps[2] + d_csrc[2], ps[3] + d_csrc[3]);
        d_pd[gw] = make_float4(pd[0] + d_cdst[0], pd[1] + d_cdst[1],
                               pd[2] + d_cdst[2], pd[3] + d_cdst[3]);
    }
}

// ---------------- K2: per-edge exp(clip(leaky_relu(s))) --------------------
__device__ __forceinline__ float att_act(float s) {
    float lr = s > 0.f ? s : LEAKY * s;
    lr = fminf(fmaxf(lr, -2.f), 2.f);
    return expf(lr);
}

__global__ void edge_exp(const int* __restrict__ src, const int* __restrict__ dst) {
    int e = blockIdx.x * blockDim.x + threadIdx.x;
    if (e >= NE) return;
    float4 a = d_ps[src[e]];
    float4 b = d_pd[dst[e]];
    d_ev[e] = make_float4(att_act(a.x + b.x), att_act(a.y + b.y),
                          att_act(a.z + b.z), att_act(a.w + b.w));
}

// ---------------- K2b: CSR row_ptr from sorted src -------------------------
__global__ void build_rowptr(const int* __restrict__ src) {
    int e = blockIdx.x * blockDim.x + threadIdx.x;
    if (e >= NE) return;
    int cur = src[e];
    int prev = (e == 0) ? -1 : src[e - 1];
    for (int n = prev + 1; n <= cur; n++) d_rowptr[n] = e;
    if (e == NE - 1)
        for (int n = cur + 1; n <= NN; n++) d_rowptr[n] = NE;
}

// ---------------- K3: bf16-split GEMM via mma.sync (HMMA) ------------------
// CTA: 256 threads / 8 warps; tile M=128 x N=128 (one head); K chunk = 64.
// A is split hi/lo from fp32 x IN REGISTERS (no conv_x pass). 3 split passes.
#define GK 64
#define PADK 72                       /* padded k-stride (bf16) -> 144B rows  */
#define TILE_B (128 * PADK * 2)       /* 18432 bytes per smem tile */
#define OFF_AHI 0
#define OFF_ALO (TILE_B)
#define OFF_BHI (2 * TILE_B)
#define OFF_BLO (3 * TILE_B)
#define SM_TOTAL (4 * TILE_B)

#define MMA_BF16(d, a, b)                                                      \
    asm volatile("mma.sync.aligned.m16n8k16.row.col.f32.bf16.bf16.f32 "        \
                 "{%0,%1,%2,%3},{%4,%5,%6,%7},{%8,%9},{%0,%1,%2,%3};"          \
                 : "+f"((d)[0]), "+f"((d)[1]), "+f"((d)[2]), "+f"((d)[3])      \
                 : "r"((a)[0]), "r"((a)[1]), "r"((a)[2]), "r"((a)[3]),         \
                   "r"((b)[0]), "r"((b)[1]))

__device__ __forceinline__ void split2(float a, float b, uint32_t& hi, uint32_t& lo) {
    __nv_bfloat162 h2, l2;
    h2.x = __float2bfloat16(a);
    h2.y = __float2bfloat16(b);
    l2.x = __float2bfloat16(a - __bfloat162float(h2.x));
    l2.y = __float2bfloat16(b - __bfloat162float(h2.y));
    hi = *reinterpret_cast<uint32_t*>(&h2);
    lo = *reinterpret_cast<uint32_t*>(&l2);
}

__global__ __launch_bounds__(256) void gemm_tc(const float* __restrict__ X,
                                               const float* __restrict__ bm) {
    extern __shared__ char smem[];
    const int tid = threadIdx.x;
    const int hx = blockIdx.x;
    const int row0 = blockIdx.y * 128;
    const int wid = tid >> 5;
    const int lane = tid & 31;
    const int gid = lane >> 2;        // 0..7
    const int tig = lane & 3;         // 0..3
    const int warpM = wid & 3;        // 4 M subtiles of 32
    const int warpN = wid >> 2;       // 2 N subtiles of 64

    const int r = tid >> 1;
    const int half = tid & 1;
    const bool inb = (row0 + r) < MTOT;
    const size_t aoff = (size_t)(row0 + r) * FIN + half * 32;   // fp32 x
    const size_t boff = ((size_t)hx * FOUT + r) * FIN + half * 32;
    const uint32_t srow = (uint32_t)(r * (PADK * 2) + half * 64);
    const uint4 z4 = make_uint4(0u, 0u, 0u, 0u);
    const float4 zf = make_float4(0.f, 0.f, 0.f, 0.f);

    float acc[2][8][4];
#pragma unroll
    for (int mt = 0; mt < 2; mt++)
#pragma unroll
        for (int nt = 0; nt < 8; nt++)
#pragma unroll
            for (int j = 0; j < 4; j++) acc[mt][nt][j] = 0.f;

    for (int kc = 0; kc < FIN / GK; kc++) {
        if (kc) __syncthreads();
#pragma unroll
        for (int j = 0; j < 4; j++) {
            size_t ge = (size_t)kc * GK + j * 8;
            uint32_t so = srow + j * 16;
            float4 v0 = inb ? *(const float4*)(X + aoff + ge) : zf;
            float4 v1 = inb ? *(const float4*)(X + aoff + ge + 4) : zf;
            uint4 ah, al;
            split2(v0.x, v0.y, ah.x, al.x);
            split2(v0.z, v0.w, ah.y, al.y);
            split2(v1.x, v1.y, ah.z, al.z);
            split2(v1.z, v1.w, ah.w, al.w);
            uint4 wh = *(const uint4*)(d_Bhi + boff + ge);
            uint4 wl = *(const uint4*)(d_Blo + boff + ge);
            *(uint4*)(smem + OFF_AHI + so) = ah;
            *(uint4*)(smem + OFF_ALO + so) = al;
            *(uint4*)(smem + OFF_BHI + so) = wh;
            *(uint4*)(smem + OFF_BLO + so) = wl;
        }
        __syncthreads();
#pragma unroll
        for (int ks = 0; ks < 4; ks++) {
            const int k0 = ks * 16;
            const uint32_t kb = (uint32_t)((k0 + tig * 2) * 2);
            uint32_t bh[8][2], bl[8][2], af[2][4];
#pragma unroll
            for (int nt = 0; nt < 8; nt++) {
                uint32_t nb = (uint32_t)((warpN * 64 + nt * 8 + gid) * (PADK * 2)) + kb;
                bh[nt][0] = *(const uint32_t*)(smem + OFF_BHI + nb);
                bh[nt][1] = *(const uint32_t*)(smem + OFF_BHI + nb + 16);
                bl[nt][0] = *(const uint32_t*)(smem + OFF_BLO + nb);
                bl[nt][1] = *(const uint32_t*)(smem + OFF_BLO + nb + 16);
            }
#pragma unroll
            for (int mt = 0; mt < 2; mt++) {
                uint32_t mb = (uint32_t)((warpM * 32 + mt * 16 + gid) * (PADK * 2)) + kb;
                af[mt][0] = *(const uint32_t*)(smem + OFF_AHI + mb);
                af[mt][1] = *(const uint32_t*)(smem + OFF_AHI + mb + 8 * (PADK * 2));
                af[mt][2] = *(const uint32_t*)(smem + OFF_AHI + mb + 16);
                af[mt][3] = *(const uint32_t*)(smem + OFF_AHI + mb + 8 * (PADK * 2) + 16);
            }
#pragma unroll
            for (int mt = 0; mt < 2; mt++)
#pragma unroll
                for (int nt = 0; nt < 8; nt++) MMA_BF16(acc[mt][nt], af[mt], bh[nt]);
#pragma unroll
            for (int mt = 0; mt < 2; mt++)
#pragma unroll
                for (int nt = 0; nt < 8; nt++) MMA_BF16(acc[mt][nt], af[mt], bl[nt]);
#pragma unroll
            for (int mt = 0; mt < 2; mt++) {
                uint32_t mb = (uint32_t)((warpM * 32 + mt * 16 + gid) * (PADK * 2)) + kb;
                af[mt][0] = *(const uint32_t*)(smem + OFF_ALO + mb);
                af[mt][1] = *(const uint32_t*)(smem + OFF_ALO + mb + 8 * (PADK * 2));
                af[mt][2] = *(const uint32_t*)(smem + OFF_ALO + mb + 16);
                af[mt][3] = *(const uint32_t*)(smem + OFF_ALO + mb + 8 * (PADK * 2) + 16);
            }
#pragma unroll
            for (int mt = 0; mt < 2; mt++)
#pragma unroll
                for (int nt = 0; nt < 8; nt++) MMA_BF16(acc[mt][nt], af[mt], bh[nt]);
        }
    }

    // ---- epilogue: bias add, convert to fp16, store node-major into d_h ----
    float2 bias[8];
#pragma unroll
    for (int nt = 0; nt < 8; nt++)
        bias[nt] = *(const float2*)(bm + hx * FOUT + warpN * 64 + nt * 8 + tig * 2);

#pragma unroll
    for (int mt = 0; mt < 2; mt++) {
#pragma unroll
        for (int rh = 0; rh < 2; rh++) {
            int gr = row0 + warpM * 32 + mt * 16 + rh * 8 + gid;
            if (gr >= MTOT) continue;
            int bb = gr / NN;
            int n = gr - bb * NN;
            __half* dp = d_h + (size_t)n * CPN + bb * (NH * FOUT) + hx * FOUT
                         + warpN * 64 + tig * 2;
#pragma unroll
            for (int nt = 0; nt < 8; nt++) {
                __half2 v = __floats2half2_rn(acc[mt][nt][rh * 2 + 0] + bias[nt].x,
                                              acc[mt][nt][rh * 2 + 1] + bias[nt].y);
                *(__half2*)(dp + nt * 8) = v;
            }
        }
    }
}

// ---------------- K4: aggregation, block per node, fp16 h ------------------
#define CHK 128
__global__ __launch_bounds__(256) void aggregate(const int* __restrict__ dst,
                                                 float* __restrict__ out) {
    const int n = blockIdx.x;
    const int r0 = d_rowptr[n];
    const int r1 = d_rowptr[n + 1];
    const int t = threadIdx.x;
    const int head = (t >> 4) & 3;        // thread's 8 halves live in one head
    __shared__ int sdst[CHK];
    __shared__ float4 sev[CHK];
    const float* evp = (const float*)sev;
    float acc[8];
#pragma unroll
    for (int j = 0; j < 8; j++) acc[j] = 0.f;
    float dacc = 0.f;

    for (int base = r0; base < r1; base += CHK) {
        int cnt = min(CHK, r1 - base);
        __syncthreads();
        if (t < cnt) {
            sdst[t] = dst[base + t];
            sev[t] = d_ev[base + t];
        }
        __syncthreads();
#pragma unroll 2
        for (int i = 0; i < cnt; i++) {
            float w = evp[i * 4 + head];
            uint4 hv = *((const uint4*)(d_h + (size_t)sdst[i] * CPN) + t);
            const __half2* h2 = (const __half2*)&hv;
            float2 f0 = __half22float2(h2[0]);
            float2 f1 = __half22float2(h2[1]);
            float2 f2 = __half22float2(h2[2]);
            float2 f3 = __half22float2(h2[3]);
            acc[0] = fmaf(w, f0.x, acc[0]);
            acc[1] = fmaf(w, f0.y, acc[1]);
            acc[2] = fmaf(w, f1.x, acc[2]);
            acc[3] = fmaf(w, f1.y, acc[3]);
            acc[4] = fmaf(w, f2.x, acc[4]);
            acc[5] = fmaf(w, f2.y, acc[5]);
            acc[6] = fmaf(w, f3.x, acc[6]);
            acc[7] = fmaf(w, f3.y, acc[7]);
            dacc += w;
        }
    }
    float inv = (r1 > r0) ? (1.0f / dacc) : 0.f;
    int bb = t >> 6;
    int c0 = (t & 63) * 8;               // within the 512 outputs of batch bb
    float* op = out + (size_t)bb * NN * (NH * FOUT) + (size_t)n * (NH * FOUT) + c0;
    float4 o0 = make_float4(acc[0] * inv, acc[1] * inv, acc[2] * inv, acc[3] * inv);
    float4 o1 = make_float4(acc[4] * inv, acc[5] * inv, acc[6] * inv, acc[7] * inv);
    *(float4*)op = o0;
    *(float4*)(op + 4) = o1;
}

// ---------------------------------------------------------------------------
extern "C" void kernel_launch(void* const* d_in, const int* in_sizes, int n_in,
                              void* d_out, int out_size) {
    const float* x   = (const float*)d_in[0];   // (B, N, 256)
    const float* Wm  = (const float*)d_in[1];   // (H, 256, 128)
    const float* bm  = (const float*)d_in[2];   // (H, 128)
    const float* Wa  = (const float*)d_in[3];   // (H, 256, 1)
    const int*   src = (const int*)d_in[4];     // (E,) sorted
    const int*   dst = (const int*)d_in[5];     // (E,)
    float* out = (float*)d_out;                 // (B, N, 512)

    cudaFuncSetAttribute(gemm_tc, cudaFuncAttributeMaxDynamicSharedMemorySize, SM_TOTAL);

    conv_w<<<(NH * FIN * FOUT + 255) / 256, 256>>>(Wm);
    prep_vecs<<<NH, 256>>>(Wm, bm, Wa);
    node_scores<<<(NN * 32 + 255) / 256, 256>>>(x + (size_t)(NB - 1) * NN * FIN);
    edge_exp<<<(NE + 255) / 256, 256>>>(src, dst);
    build_rowptr<<<(NE + 255) / 256, 256>>>(src);
    dim3 gg(NH, (MTOT + 127) / 128);
    gemm_tc<<<gg, 256, SM_TOTAL>>>(x, bm);
    aggregate<<<NN, 256>>>(dst, out);
}